// round 6
// baseline (speedup 1.0000x reference)
#include <cuda_runtime.h>
#include <math.h>

// Problem constants (B=2,S=2048 -> T=4096; H=1024; F=4096; E=8; TOP_K=2)
#define Tt 4096
#define Hh 1024
#define Ff 4096
#define Ee 8

// ---------------- scratch (static device globals; no allocation) ----------------
__device__ float  g_mid[(size_t)3 * Tt * Ff];      // base mid [0,T), expert mids [T,3T); tf32-rounded
__device__ float  g_xtf[(size_t)Tt * Hh];          // x, tf32-rounded
__device__ float  g_xg [(size_t)2 * Tt * Hh];      // gathered expert A rows (tf32)
__device__ float  g_expout[(size_t)2 * Tt * Hh];   // unweighted expert outputs
__device__ int    g_tok[Ee * Tt];
__device__ int    g_cnt[Ee];
__device__ int    g_off[Ee];
__device__ int4   g_sel[Tt];
__device__ float2 g_wt[Tt];

// ---------------- helpers ----------------
__device__ __forceinline__ unsigned f2tf(float f) {
    unsigned u;
    asm("cvt.rna.tf32.f32 %0, %1;" : "=r"(u) : "f"(f));
    return u;
}
__device__ __forceinline__ unsigned f2tf_u(unsigned raw) {
    unsigned u;
    asm("cvt.rna.tf32.f32 %0, %1;" : "=r"(u) : "f"(__uint_as_float(raw)));
    return u;
}

__device__ __forceinline__ void mma8(float* c, const unsigned* a, const unsigned* b) {
    asm volatile(
        "mma.sync.aligned.m16n8k8.row.col.f32.tf32.tf32.f32 "
        "{%0,%1,%2,%3}, {%4,%5,%6,%7}, {%8,%9}, {%0,%1,%2,%3};"
        : "+f"(c[0]), "+f"(c[1]), "+f"(c[2]), "+f"(c[3])
        : "r"(a[0]), "r"(a[1]), "r"(a[2]), "r"(a[3]),
          "r"(b[0]), "r"(b[1]));
}

__device__ __forceinline__ void cp16(unsigned smem_addr, const void* gptr, int srcsize) {
    asm volatile("cp.async.cg.shared.global [%0], [%1], 16, %2;"
                 :: "r"(smem_addr), "l"(gptr), "r"(srcsize));
}
__device__ __forceinline__ void cp_commit() { asm volatile("cp.async.commit_group;"); }
template <int N>
__device__ __forceinline__ void cp_wait() {
    asm volatile("cp.async.wait_group %0;" :: "n"(N));
}

// ---------------- small kernels ----------------
__global__ void zero_cnt_kernel() {
    if (threadIdx.x < Ee) g_cnt[threadIdx.x] = 0;
}

__global__ void router_kernel(const float* __restrict__ x, const float* __restrict__ rw) {
    int wid  = threadIdx.x >> 5;
    int lane = threadIdx.x & 31;
    int t = blockIdx.x * 8 + wid;
    if (t >= Tt) return;

    float acc[8] = {0.f,0.f,0.f,0.f,0.f,0.f,0.f,0.f};
    const float* xr = x + (size_t)t * Hh;
    for (int h = lane; h < Hh; h += 32) {
        float xv = xr[h];
        float4 r0 = *(const float4*)(rw + (size_t)h * Ee);
        float4 r1 = *(const float4*)(rw + (size_t)h * Ee + 4);
        acc[0] += xv * r0.x; acc[1] += xv * r0.y; acc[2] += xv * r0.z; acc[3] += xv * r0.w;
        acc[4] += xv * r1.x; acc[5] += xv * r1.y; acc[6] += xv * r1.z; acc[7] += xv * r1.w;
    }
#pragma unroll
    for (int e = 0; e < 8; e++)
#pragma unroll
        for (int o = 16; o > 0; o >>= 1)
            acc[e] += __shfl_xor_sync(0xffffffffu, acc[e], o);

    if (lane == 0) {
        float m = acc[0];
#pragma unroll
        for (int e = 1; e < 8; e++) m = fmaxf(m, acc[e]);
        float p[8];
#pragma unroll
        for (int e = 0; e < 8; e++) p[e] = expf(acc[e] - m);
        int i0 = 0; float b0 = p[0];
#pragma unroll
        for (int e = 1; e < 8; e++) if (p[e] > b0) { b0 = p[e]; i0 = e; }
        int i1 = -1; float b1 = -1.f;
#pragma unroll
        for (int e = 0; e < 8; e++) if (e != i0 && p[e] > b1) { b1 = p[e]; i1 = e; }
        float inv = 1.f / (b0 + b1);
        int s0 = atomicAdd(&g_cnt[i0], 1); g_tok[i0 * Tt + s0] = t;
        int s1 = atomicAdd(&g_cnt[i1], 1); g_tok[i1 * Tt + s1] = t;
        g_sel[t] = make_int4(i0, s0, i1, s1);
        g_wt[t]  = make_float2(b0 * inv, b1 * inv);
    }
}

__global__ void scan_kernel() {
    if (threadIdx.x == 0) {
        int o = 0;
        for (int e = 0; e < Ee; e++) { g_off[e] = o; o += g_cnt[e]; }
    }
}

__global__ void gather_kernel(const float* __restrict__ x) {
    int t = blockIdx.x;
    int4 s = g_sel[t];
    size_t p0 = (size_t)(g_off[s.x] + s.y) * Hh;
    size_t p1 = (size_t)(g_off[s.z] + s.w) * Hh;
    int i = threadIdx.x;
    float4 v = *(const float4*)(x + (size_t)t * Hh + i * 4);
    v.x = __uint_as_float(f2tf(v.x));
    v.y = __uint_as_float(f2tf(v.y));
    v.z = __uint_as_float(f2tf(v.z));
    v.w = __uint_as_float(f2tf(v.w));
    *(float4*)(g_xtf + (size_t)t * Hh + i * 4) = v;
    *(float4*)(g_xg + p0 + i * 4) = v;
    *(float4*)(g_xg + p1 + i * 4) = v;
}

// ---------------- grouped GEMM: CTA 128x256, warp tile 64x64, 2-stage cp.async ----------------
// MODE 1: g_mid = tf32(silu(A @ W1)),  A = g_xtf / g_xg+off,  K=H, N=F
// MODE 2: out   = A @ W2,              A = g_mid rows,        K=F, N=H
#define AS_W (128 * 36)           // A stage: 128 rows x 32k, stride 36 -> 4608 words
#define BS_W (32 * 264)           // B stage: 32 k-rows x 256n, stride 264 -> 8448 words
#define STG_W (AS_W + BS_W)       // 13056 words = 52224 B per stage

template <int MODE>
__global__ void __launch_bounds__(256, 1) gemm_kernel(
    float* __restrict__ Dout,
    const float* __restrict__ Wbase,
    const float* __restrict__ Wexp)
{
    constexpr int Kd = (MODE == 1) ? Hh : Ff;
    constexpr int Nd = (MODE == 1) ? Ff : Hh;
    constexpr int NT = Kd / 32;

    extern __shared__ unsigned sm[];   // 2 stages x [A | B]

    const int g  = blockIdx.z;
    const int tm = blockIdx.x;
    const int tn = blockIdx.y;
    const int e  = g - 1;
    const int cnt = (g == 0) ? Tt : g_cnt[e];
    if (tm * 128 >= cnt) return;
    const int off = (g == 0) ? 0 : g_off[e];

    const float* Bsrc = (g == 0) ? Wbase : (Wexp + (size_t)e * Kd * Nd);
    const float* Abase;
    float* Outp;
    if (MODE == 1) {
        Abase = (g == 0) ? g_xtf : (g_xg + (size_t)off * Hh);
        Outp  = g_mid + ((g == 0) ? 0 : (size_t)(Tt + off) * Ff);
    } else {
        Abase = g_mid + ((g == 0) ? 0 : (size_t)(Tt + off) * Ff);
        Outp  = (g == 0) ? Dout : (g_expout + (size_t)off * Hh);
    }

    const int tid  = threadIdx.x;
    const int lane = tid & 31;
    const int wid  = tid >> 5;
    const int wm = wid & 1, wn = wid >> 1;   // warps: 2(m) x 4(n); warp tile 64x64
    const int g8 = lane >> 2, tq = lane & 3;

    // ---- loader mapping ----
    // A: 128 rows x 8 chunks(16B). thread -> (row=tid>>3 in 32-row pass, chunk=tid&7). 4 passes.
    const int ar = tid >> 3;
    const int ac = (tid & 7) * 4;
    // B: 32 k-rows x 64 chunks. thread -> (k=tid>>5, chunk=tid&31). 4 k-passes x 2 col-passes.
    const int bkr = tid >> 5;
    const int bc  = (tid & 31) * 4;

    const float* aptr[4];
    int asz[4];
#pragma unroll
    for (int p = 0; p < 4; p++) {
        int row = tm * 128 + p * 32 + ar;
        int ok = row < cnt;
        aptr[p] = Abase + (size_t)(ok ? row : 0) * Kd + ac;
        asz[p] = ok ? 16 : 0;
    }
    const float* bptr = Bsrc + (size_t)bkr * Nd + tn * 256 + bc;

    unsigned a_dst, b_dst;
    {
        unsigned base = (unsigned)__cvta_generic_to_shared(sm);
        a_dst = base + (ar * 36 + ac) * 4;
        b_dst = base + (AS_W + bkr * 264 + bc) * 4;
    }

    auto issue = [&](int kidx) {
        int stage = kidx & 1;
        unsigned ad = a_dst + stage * (STG_W * 4);
        unsigned bd = b_dst + stage * (STG_W * 4);
        int akoff = kidx * 32;
        size_t bkoff = (size_t)kidx * 32 * Nd;
#pragma unroll
        for (int p = 0; p < 4; p++)
            cp16(ad + p * (32 * 36 * 4), aptr[p] + akoff, asz[p]);
#pragma unroll
        for (int kp = 0; kp < 4; kp++)       // k-rows bkr, bkr+8, bkr+16, bkr+24
#pragma unroll
            for (int cpn = 0; cpn < 2; cpn++) // chunk cols bc, bc+128
                cp16(bd + (kp * 8 * 264 + cpn * 128) * 4,
                     bptr + bkoff + (size_t)kp * 8 * Nd + cpn * 128, 16);
        cp_commit();
    };

    issue(0);
    issue(1);

    float C[4][8][4];
#pragma unroll
    for (int i = 0; i < 4; i++)
#pragma unroll
        for (int j = 0; j < 8; j++)
#pragma unroll
            for (int q = 0; q < 4; q++) C[i][j][q] = 0.f;

#pragma unroll 1
    for (int it = 0; it < NT; it++) {
        cp_wait<1>();
        __syncthreads();

        const unsigned* Asl = sm + (it & 1) * STG_W;
        const unsigned* Bsl = Asl + AS_W;

#pragma unroll
        for (int kk = 0; kk < 32; kk += 8) {
            unsigned a[4][4], b[8][2];
#pragma unroll
            for (int i = 0; i < 4; i++) {
                int r = wm * 64 + i * 16 + g8;
                a[i][0] = Asl[r * 36 + kk + tq];
                a[i][1] = Asl[(r + 8) * 36 + kk + tq];
                a[i][2] = Asl[r * 36 + kk + tq + 4];
                a[i][3] = Asl[(r + 8) * 36 + kk + tq + 4];
            }
#pragma unroll
            for (int j = 0; j < 8; j++) {
                int cc = wn * 64 + j * 8 + g8;
                b[j][0] = f2tf_u(Bsl[(kk + tq) * 264 + cc]);
                b[j][1] = f2tf_u(Bsl[(kk + tq + 4) * 264 + cc]);
            }
#pragma unroll
            for (int i = 0; i < 4; i++)
#pragma unroll
                for (int j = 0; j < 8; j++)
                    mma8(C[i][j], a[i], b[j]);
        }

        __syncthreads();
        if (it + 2 < NT) issue(it + 2);
    }

    // ---- epilogue (GLOBAL rows) ----
#pragma unroll
    for (int i = 0; i < 4; i++) {
        int r0 = tm * 128 + wm * 64 + i * 16 + g8;
        int r1 = r0 + 8;
        int ok0 = r0 < cnt;
        int ok1 = r1 < cnt;
#pragma unroll
        for (int j = 0; j < 8; j++) {
            int col = tn * 256 + wn * 64 + j * 8 + 2 * tq;
            float v0 = C[i][j][0], v1 = C[i][j][1];
            float v2 = C[i][j][2], v3 = C[i][j][3];
            if (MODE == 1) {
                v0 = __uint_as_float(f2tf(v0 / (1.f + __expf(-v0))));
                v1 = __uint_as_float(f2tf(v1 / (1.f + __expf(-v1))));
                v2 = __uint_as_float(f2tf(v2 / (1.f + __expf(-v2))));
                v3 = __uint_as_float(f2tf(v3 / (1.f + __expf(-v3))));
            }
            if (ok0) *(float2*)(Outp + (size_t)r0 * Nd + col) = make_float2(v0, v1);
            if (ok1) *(float2*)(Outp + (size_t)r1 * Nd + col) = make_float2(v2, v3);
        }
    }
}

// out[t] += w0*expout[p0] + w1*expout[p1]
__global__ void combine_kernel(float* __restrict__ out) {
    int t = blockIdx.x;
    int4 s = g_sel[t];
    float2 w = g_wt[t];
    int p0 = g_off[s.x] + s.y;
    int p1 = g_off[s.z] + s.w;
    const float4* a = (const float4*)(g_expout + (size_t)p0 * Hh);
    const float4* b = (const float4*)(g_expout + (size_t)p1 * Hh);
    float4* o = (float4*)(out + (size_t)t * Hh);
    int i = threadIdx.x;
    float4 ov = o[i], av = a[i], bv = b[i];
    ov.x += w.x * av.x + w.y * bv.x;
    ov.y += w.x * av.y + w.y * bv.y;
    ov.z += w.x * av.z + w.y * bv.z;
    ov.w += w.x * av.w + w.y * bv.w;
    o[i] = ov;
}

// ---------------- launch ----------------
extern "C" void kernel_launch(void* const* d_in, const int* in_sizes, int n_in,
                              void* d_out, int out_size)
{
    const float* x   = (const float*)d_in[0];
    const float* rw  = (const float*)d_in[1];
    const float* bw1 = (const float*)d_in[2];
    const float* bw2 = (const float*)d_in[3];
    const float* ew1 = (const float*)d_in[4];
    const float* ew2 = (const float*)d_in[5];
    float* out = (float*)d_out;

    // Idempotent (no static guards; graph-capture safe).
    const int smem_bytes = 2 * STG_W * 4;   // 104,448 B
    cudaFuncSetAttribute(gemm_kernel<1>, cudaFuncAttributeMaxDynamicSharedMemorySize, smem_bytes);
    cudaFuncSetAttribute(gemm_kernel<2>, cudaFuncAttributeMaxDynamicSharedMemorySize, smem_bytes);

    zero_cnt_kernel<<<1, 32>>>();
    router_kernel<<<Tt / 8, 256>>>(x, rw);
    scan_kernel<<<1, 32>>>();
    gather_kernel<<<Tt, 256>>>(x);

    // GEMM1: grid (m=32, n=F/256=16, groups=9)
    gemm_kernel<1><<<dim3(32, 16, Ee + 1), 256, smem_bytes>>>(nullptr, bw1, ew1);
    // GEMM2: grid (m=32, n=H/256=4, groups=9)
    gemm_kernel<2><<<dim3(32, 4, Ee + 1), 256, smem_bytes>>>(out, bw2, ew2);

    combine_kernel<<<Tt, 256>>>(out);
}

// round 14
// speedup vs baseline: 1.3942x; 1.3942x over previous
#include <cuda_runtime.h>
#include <cuda_fp16.h>
#include <math.h>

// Problem constants (B=2,S=2048 -> T=4096; H=1024; F=4096; E=8; TOP_K=2)
#define Tt 4096
#define Hh 1024
#define Ff 4096
#define Ee 8

// ---------------- scratch (static device globals, ~294 MB) ----------------
// RULE (session finding): __device__ symbols must NEVER be passed as kernel
// arguments from host code (host shadow address != device address).
// All globals below are referenced ONLY inside device code.
__device__ __half  g_w1t[(size_t)(Ee + 1) * Ff * Hh];   // W1^T per group: [g][F][H] fp16
__device__ __half  g_w2t[(size_t)(Ee + 1) * Hh * Ff];   // W2^T per group: [g][H][F] fp16
__device__ __half  g_midh[(size_t)3 * Tt * Ff];         // fp16 mid: base [0,T), experts [T,3T)
__device__ __half  g_xh [(size_t)Tt * Hh];              // fp16 x
__device__ float   g_expof[(size_t)2 * Tt * Hh];        // fp32 unweighted expert outputs
__device__ int     g_tok[Ee * Tt];
__device__ int     g_cnt[Ee];
__device__ int     g_off[Ee];
__device__ int4    g_sel[Tt];                           // (e0, slot0, e1, slot1)
__device__ float2  g_wt[Tt];

// ---------------- PTX helpers ----------------
__device__ __forceinline__ void mmah(float* c, const unsigned* a, const unsigned* b) {
    asm volatile(
        "mma.sync.aligned.m16n8k16.row.col.f32.f16.f16.f32 "
        "{%0,%1,%2,%3}, {%4,%5,%6,%7}, {%8,%9}, {%0,%1,%2,%3};"
        : "+f"(c[0]), "+f"(c[1]), "+f"(c[2]), "+f"(c[3])
        : "r"(a[0]), "r"(a[1]), "r"(a[2]), "r"(a[3]),
          "r"(b[0]), "r"(b[1]));
}
__device__ __forceinline__ void cp16(unsigned smem_addr, const void* gptr, int srcsize) {
    asm volatile("cp.async.cg.shared.global [%0], [%1], 16, %2;"
                 :: "r"(smem_addr), "l"(gptr), "r"(srcsize));
}
__device__ __forceinline__ void cp_commit() { asm volatile("cp.async.commit_group;"); }
template <int N>
__device__ __forceinline__ void cp_wait() {
    asm volatile("cp.async.wait_group %0;" :: "n"(N));
}

// ---------------- small kernels ----------------
__global__ void zero_cnt_kernel() {
    if (threadIdx.x < Ee) g_cnt[threadIdx.x] = 0;
}

// one warp per token: logits, softmax, top2, renormalize, slot assignment (fp32 exact)
__global__ void router_kernel(const float* __restrict__ x, const float* __restrict__ rw) {
    int wid  = threadIdx.x >> 5;
    int lane = threadIdx.x & 31;
    int t = blockIdx.x * 8 + wid;
    if (t >= Tt) return;

    float acc[8] = {0.f,0.f,0.f,0.f,0.f,0.f,0.f,0.f};
    const float* xr = x + (size_t)t * Hh;
    for (int h = lane; h < Hh; h += 32) {
        float xv = xr[h];
        float4 r0 = *(const float4*)(rw + (size_t)h * Ee);
        float4 r1 = *(const float4*)(rw + (size_t)h * Ee + 4);
        acc[0] += xv * r0.x; acc[1] += xv * r0.y; acc[2] += xv * r0.z; acc[3] += xv * r0.w;
        acc[4] += xv * r1.x; acc[5] += xv * r1.y; acc[6] += xv * r1.z; acc[7] += xv * r1.w;
    }
#pragma unroll
    for (int e = 0; e < 8; e++)
#pragma unroll
        for (int o = 16; o > 0; o >>= 1)
            acc[e] += __shfl_xor_sync(0xffffffffu, acc[e], o);

    if (lane == 0) {
        float m = acc[0];
#pragma unroll
        for (int e = 1; e < 8; e++) m = fmaxf(m, acc[e]);
        float p[8];
#pragma unroll
        for (int e = 0; e < 8; e++) p[e] = expf(acc[e] - m);
        int i0 = 0; float b0 = p[0];
#pragma unroll
        for (int e = 1; e < 8; e++) if (p[e] > b0) { b0 = p[e]; i0 = e; }
        int i1 = -1; float b1 = -1.f;
#pragma unroll
        for (int e = 0; e < 8; e++) if (e != i0 && p[e] > b1) { b1 = p[e]; i1 = e; }
        float inv = 1.f / (b0 + b1);
        int s0 = atomicAdd(&g_cnt[i0], 1); g_tok[i0 * Tt + s0] = t;
        int s1 = atomicAdd(&g_cnt[i1], 1); g_tok[i1 * Tt + s1] = t;
        g_sel[t] = make_int4(i0, s0, i1, s1);
        g_wt[t]  = make_float2(b0 * inv, b1 * inv);
    }
}

__global__ void scan_kernel() {
    if (threadIdx.x == 0) {
        int o = 0;
        for (int e = 0; e < Ee; e++) { g_off[e] = o; o += g_cnt[e]; }
    }
}

// x fp32 -> fp16 into g_xh (expert rows gathered in GEMM1 via g_tok)
__global__ void convx_kernel(const float* __restrict__ x) {
    int t = blockIdx.x;
    int i = threadIdx.x;               // 256 threads x 4 elems = 1024
    float4 v = *(const float4*)(x + (size_t)t * Hh + i * 4);
    __half2 h0 = __floats2half2_rn(v.x, v.y);
    __half2 h1 = __floats2half2_rn(v.z, v.w);
    *(uint2*)(g_xh + (size_t)t * Hh + i * 4) = make_uint2(*(unsigned*)&h0, *(unsigned*)&h1);
}

// transpose + fp16-convert: src[g][R][C] fp32 -> (g_w1t or g_w2t)[g][C][R] fp16.
// Destination selected INSIDE device code via template (never passed from host).
template <int W>
__global__ void transw_kernel(const float* __restrict__ base,
                              const float* __restrict__ exq) {
    constexpr int R = (W == 1) ? Hh : Ff;
    constexpr int C = (W == 1) ? Ff : Hh;
    __shared__ float tile[32][33];
    int g = blockIdx.z;
    const float* src = (g == 0) ? base : (exq + (size_t)(g - 1) * R * C);
    __half* d = ((W == 1) ? g_w1t : g_w2t) + (size_t)g * (size_t)R * C;
    int c0 = blockIdx.x * 32, r0 = blockIdx.y * 32;
    int tx = threadIdx.x, ty = threadIdx.y;
#pragma unroll
    for (int i = ty; i < 32; i += 8)
        tile[i][tx] = src[(size_t)(r0 + i) * C + c0 + tx];
    __syncthreads();
#pragma unroll
    for (int i = ty; i < 32; i += 8)
        d[(size_t)(c0 + i) * R + r0 + tx] = __float2half_rn(tile[tx][i]);
}

// ---------------- grouped fp16 GEMM: CTA 128x128, warp 64x32, 2-stage cp.async ----------------
// Both operands K-contiguous in smem; every mma fragment register = one scalar LDS.32.
// MODE 1: g_midh = fp16(silu(A @ W1t^T)),  A rows = tokens (g_tok gather for experts), K=H, N=F
// MODE 2: fp32 out: base -> Dout, experts -> g_expof. A = g_midh rows, K=F, N=H
// smem rows: 32 halves (16 words) padded to 20 words -> banks (20r+tq)%32 all-distinct
#define ROW_W 20                      // words per smem row
#define A_STG_W (128 * ROW_W)         // 2560 words
#define STG_W (2 * A_STG_W)           // A + B = 5120 words = 20480 B; 2 stages = 40960 B

template <int MODE>
__global__ void __launch_bounds__(256, 2) gemm_kernel(
    float* __restrict__ Dout)
{
    constexpr int Kd = (MODE == 1) ? Hh : Ff;
    constexpr int Nd = (MODE == 1) ? Ff : Hh;
    constexpr int NT = Kd / 32;

    extern __shared__ unsigned sm[];
    __shared__ int s_arow[128];

    const int g  = blockIdx.z;
    const int tm = blockIdx.x;
    const int tn = blockIdx.y;
    const int e  = g - 1;
    const int cnt = (g == 0) ? Tt : g_cnt[e];
    if (tm * 128 >= cnt) return;
    const int off = (g == 0) ? 0 : g_off[e];

    const __half* Bt = ((MODE == 1) ? g_w1t : g_w2t) + (size_t)g * (size_t)Hh * Ff;
    const __half* Abase;
    float* OutpF = nullptr;
    __half* OutpH = nullptr;
    if (MODE == 1) {
        Abase = g_xh;                                   // token rows (gathered via s_arow)
        OutpH = g_midh + ((g == 0) ? 0 : (size_t)(Tt + off) * Ff);
    } else {
        Abase = g_midh + ((g == 0) ? 0 : (size_t)(Tt + off) * Ff);
        OutpF = (g == 0) ? Dout : (g_expof + (size_t)off * Hh);
    }

    const int tid  = threadIdx.x;
    const int lane = tid & 31;
    const int wid  = tid >> 5;
    const int wm = wid & 1, wn = wid >> 1;   // warps 2(m) x 4(n); warp tile 64x32
    const int g8 = lane >> 2, tq = lane & 3;

    // ---- A row indirection (token gather for MODE1 experts; identity otherwise) ----
    if (tid < 128) {
        int idx = tm * 128 + tid;
        int r = -1;
        if (idx < cnt) r = (MODE == 1) ? ((g == 0) ? idx : g_tok[e * Tt + idx]) : idx;
        s_arow[tid] = r;
    }
    __syncthreads();

    // ---- cp.async loader mapping: thread -> (row=tid>>2 [64/pass], chunk=tid&3) ----
    const int lrow = tid >> 2;
    const int lchk = tid & 3;

    const __half* aptr[2];
    int asz[2];
#pragma unroll
    for (int p = 0; p < 2; p++) {
        int srow = s_arow[p * 64 + lrow];
        aptr[p] = Abase + (size_t)(srow < 0 ? 0 : srow) * Kd + lchk * 8;
        asz[p] = (srow < 0) ? 0 : 16;
    }
    const __half* bptr[2];
#pragma unroll
    for (int p = 0; p < 2; p++)
        bptr[p] = Bt + (size_t)(tn * 128 + p * 64 + lrow) * Kd + lchk * 8;

    unsigned a_dst, b_dst;
    {
        unsigned base = (unsigned)__cvta_generic_to_shared(sm);
        a_dst = base + (lrow * ROW_W + lchk * 4) * 4;
        b_dst = base + (A_STG_W + lrow * ROW_W + lchk * 4) * 4;
    }

    auto issue = [&](int kidx) {
        unsigned so = (kidx & 1) * (STG_W * 4);
        int kh = kidx * 32;                       // k offset in halves
#pragma unroll
        for (int p = 0; p < 2; p++)
            cp16(a_dst + so + p * (64 * ROW_W * 4), aptr[p] + kh, asz[p]);
#pragma unroll
        for (int p = 0; p < 2; p++)
            cp16(b_dst + so + p * (64 * ROW_W * 4), bptr[p] + kh, 16);
        cp_commit();
    };

    issue(0);
    issue(1);

    float C[4][4][4];
#pragma unroll
    for (int i = 0; i < 4; i++)
#pragma unroll
        for (int j = 0; j < 4; j++)
#pragma unroll
            for (int q = 0; q < 4; q++) C[i][j][q] = 0.f;

#pragma unroll 1
    for (int it = 0; it < NT; it++) {
        // With the tail empty-commits below, wait<1> here ALWAYS implies
        // k-chunk `it` is fully resident (group it is never the newest).
        cp_wait<1>();
        __syncthreads();

        const unsigned* Asl = sm + (it & 1) * STG_W;
        const unsigned* Bsl = Asl + A_STG_W;

#pragma unroll
        for (int s = 0; s < 2; s++) {            // two k16 steps per 32-k chunk
            unsigned a[4][4], b[4][2];
#pragma unroll
            for (int i = 0; i < 4; i++) {
                int r = wm * 64 + i * 16 + g8;
                a[i][0] = Asl[r * ROW_W + 8 * s + tq];            // (m,   k0-7 pair tq)
                a[i][1] = Asl[(r + 8) * ROW_W + 8 * s + tq];      // (m+8, k0-7)
                a[i][2] = Asl[r * ROW_W + 8 * s + tq + 4];        // (m,   k8-15)
                a[i][3] = Asl[(r + 8) * ROW_W + 8 * s + tq + 4];  // (m+8, k8-15)
            }
#pragma unroll
            for (int j = 0; j < 4; j++) {
                int n = wn * 32 + j * 8 + g8;
                b[j][0] = Bsl[n * ROW_W + 8 * s + tq];            // (n, k0-7)
                b[j][1] = Bsl[n * ROW_W + 8 * s + tq + 4];        // (n, k8-15)
            }
#pragma unroll
            for (int i = 0; i < 4; i++)
#pragma unroll
                for (int j = 0; j < 4; j++)
                    mmah(C[i][j], a[i], b[j]);
        }

        __syncthreads();
        if (it + 2 < NT) issue(it + 2);
        else             cp_commit();   // empty group: keeps group it from being newest
    }

    // ---- epilogue (global rows) ----
#pragma unroll
    for (int i = 0; i < 4; i++) {
        int gr0 = tm * 128 + wm * 64 + i * 16 + g8;
        int ok0 = gr0 < cnt;
        int ok1 = (gr0 + 8) < cnt;
#pragma unroll
        for (int j = 0; j < 4; j++) {
            int col = tn * 128 + wn * 32 + j * 8 + 2 * tq;
            float v0 = C[i][j][0], v1 = C[i][j][1];
            float v2 = C[i][j][2], v3 = C[i][j][3];
            if (MODE == 1) {
                v0 = v0 / (1.f + __expf(-v0));
                v1 = v1 / (1.f + __expf(-v1));
                v2 = v2 / (1.f + __expf(-v2));
                v3 = v3 / (1.f + __expf(-v3));
                __half2 h0 = __floats2half2_rn(v0, v1);
                __half2 h1 = __floats2half2_rn(v2, v3);
                if (ok0) *(unsigned*)(OutpH + (size_t)gr0 * Nd + col) = *(unsigned*)&h0;
                if (ok1) *(unsigned*)(OutpH + (size_t)(gr0 + 8) * Nd + col) = *(unsigned*)&h1;
            } else {
                if (ok0) *(float2*)(OutpF + (size_t)gr0 * Nd + col) = make_float2(v0, v1);
                if (ok1) *(float2*)(OutpF + (size_t)(gr0 + 8) * Nd + col) = make_float2(v2, v3);
            }
        }
    }
}

// out[t] += w0*expof[p0] + w1*expof[p1]   (fp32 expert outputs)
__global__ void combine_kernel(float* __restrict__ out) {
    int t = blockIdx.x;
    int4 s = g_sel[t];
    float2 w = g_wt[t];
    int p0 = g_off[s.x] + s.y;
    int p1 = g_off[s.z] + s.w;
    const float4* a = (const float4*)(g_expof + (size_t)p0 * Hh);
    const float4* b = (const float4*)(g_expof + (size_t)p1 * Hh);
    float4* o = (float4*)(out + (size_t)t * Hh);
    int i = threadIdx.x;   // 256 threads x 4 floats = 1024
    float4 ov = o[i], av = a[i], bv = b[i];
    ov.x += w.x * av.x + w.y * bv.x;
    ov.y += w.x * av.y + w.y * bv.y;
    ov.z += w.x * av.z + w.y * bv.z;
    ov.w += w.x * av.w + w.y * bv.w;
    o[i] = ov;
}

// ---------------- launch ----------------
extern "C" void kernel_launch(void* const* d_in, const int* in_sizes, int n_in,
                              void* d_out, int out_size)
{
    const float* x   = (const float*)d_in[0];
    const float* rw  = (const float*)d_in[1];
    const float* bw1 = (const float*)d_in[2];
    const float* bw2 = (const float*)d_in[3];
    const float* ew1 = (const float*)d_in[4];
    const float* ew2 = (const float*)d_in[5];
    float* out = (float*)d_out;

    // Idempotent (no static guards; graph-capture safe). Function symbols are OK here.
    const int smem_bytes = 2 * STG_W * 4;   // 40,960 B
    cudaFuncSetAttribute(gemm_kernel<1>, cudaFuncAttributeMaxDynamicSharedMemorySize, smem_bytes);
    cudaFuncSetAttribute(gemm_kernel<2>, cudaFuncAttributeMaxDynamicSharedMemorySize, smem_bytes);

    zero_cnt_kernel<<<1, 32>>>();
    router_kernel<<<Tt / 8, 256>>>(x, rw);
    scan_kernel<<<1, 32>>>();
    convx_kernel<<<Tt, 256>>>(x);

    // W1 [H][F] -> g_w1t [F][H] fp16 ; W2 [F][H] -> g_w2t [H][F] fp16
    transw_kernel<1><<<dim3(Ff / 32, Hh / 32, Ee + 1), dim3(32, 8)>>>(bw1, ew1);
    transw_kernel<2><<<dim3(Hh / 32, Ff / 32, Ee + 1), dim3(32, 8)>>>(bw2, ew2);

    // GEMM1: grid (m=32, n=F/128=32, groups=9)
    gemm_kernel<1><<<dim3(32, 32, Ee + 1), 256, smem_bytes>>>(nullptr);
    // GEMM2: grid (m=32, n=H/128=8, groups=9)
    gemm_kernel<2><<<dim3(32, 8, Ee + 1), 256, smem_bytes>>>(out);

    combine_kernel<<<Tt, 256>>>(out);
}

// round 15
// speedup vs baseline: 1.4656x; 1.0513x over previous
#include <cuda_runtime.h>
#include <cuda_fp16.h>
#include <math.h>

// Problem constants (B=2,S=2048 -> T=4096; H=1024; F=4096; E=8; TOP_K=2)
#define Tt 4096
#define Hh 1024
#define Ff 4096
#define Ee 8

// ---------------- scratch (static device globals, ~294 MB) ----------------
// RULE (session finding): __device__ symbols must NEVER be passed as kernel
// arguments from host code (host shadow address != device address).
// All globals below are referenced ONLY inside device code.
__device__ __half  g_w1t[(size_t)(Ee + 1) * Ff * Hh];   // W1^T per group: [g][F][H] fp16
__device__ __half  g_w2t[(size_t)(Ee + 1) * Hh * Ff];   // W2^T per group: [g][H][F] fp16
__device__ __half  g_midh[(size_t)3 * Tt * Ff];         // fp16 mid: base [0,T), experts [T,3T)
__device__ __half  g_xh [(size_t)Tt * Hh];              // fp16 x
__device__ float   g_expof[(size_t)2 * Tt * Hh];        // fp32 unweighted expert outputs
__device__ int     g_tok[Ee * Tt];
__device__ int     g_cnt[Ee];
__device__ int     g_off[Ee];
__device__ int4    g_sel[Tt];                           // (e0, slot0, e1, slot1)
__device__ float2  g_wt[Tt];

// ---------------- PTX helpers ----------------
__device__ __forceinline__ void mmah(float* c, const unsigned* a, const unsigned* b) {
    asm volatile(
        "mma.sync.aligned.m16n8k16.row.col.f32.f16.f16.f32 "
        "{%0,%1,%2,%3}, {%4,%5,%6,%7}, {%8,%9}, {%0,%1,%2,%3};"
        : "+f"(c[0]), "+f"(c[1]), "+f"(c[2]), "+f"(c[3])
        : "r"(a[0]), "r"(a[1]), "r"(a[2]), "r"(a[3]),
          "r"(b[0]), "r"(b[1]));
}
__device__ __forceinline__ void ldsm4(unsigned& r0, unsigned& r1, unsigned& r2, unsigned& r3,
                                      unsigned addr) {
    asm volatile("ldmatrix.sync.aligned.m8n8.x4.shared.b16 {%0,%1,%2,%3}, [%4];"
                 : "=r"(r0), "=r"(r1), "=r"(r2), "=r"(r3) : "r"(addr));
}
__device__ __forceinline__ void cp16(unsigned smem_addr, const void* gptr, int srcsize) {
    asm volatile("cp.async.cg.shared.global [%0], [%1], 16, %2;"
                 :: "r"(smem_addr), "l"(gptr), "r"(srcsize));
}
__device__ __forceinline__ void cp_commit() { asm volatile("cp.async.commit_group;"); }
template <int N>
__device__ __forceinline__ void cp_wait() {
    asm volatile("cp.async.wait_group %0;" :: "n"(N));
}

// ---------------- small kernels ----------------
__global__ void zero_cnt_kernel() {
    if (threadIdx.x < Ee) g_cnt[threadIdx.x] = 0;
}

// one warp per token: logits, softmax, top2, renormalize, slot assignment (fp32 exact)
__global__ void router_kernel(const float* __restrict__ x, const float* __restrict__ rw) {
    int wid  = threadIdx.x >> 5;
    int lane = threadIdx.x & 31;
    int t = blockIdx.x * 8 + wid;
    if (t >= Tt) return;

    float acc[8] = {0.f,0.f,0.f,0.f,0.f,0.f,0.f,0.f};
    const float* xr = x + (size_t)t * Hh;
    for (int h = lane; h < Hh; h += 32) {
        float xv = xr[h];
        float4 r0 = *(const float4*)(rw + (size_t)h * Ee);
        float4 r1 = *(const float4*)(rw + (size_t)h * Ee + 4);
        acc[0] += xv * r0.x; acc[1] += xv * r0.y; acc[2] += xv * r0.z; acc[3] += xv * r0.w;
        acc[4] += xv * r1.x; acc[5] += xv * r1.y; acc[6] += xv * r1.z; acc[7] += xv * r1.w;
    }
#pragma unroll
    for (int e = 0; e < 8; e++)
#pragma unroll
        for (int o = 16; o > 0; o >>= 1)
            acc[e] += __shfl_xor_sync(0xffffffffu, acc[e], o);

    if (lane == 0) {
        float m = acc[0];
#pragma unroll
        for (int e = 1; e < 8; e++) m = fmaxf(m, acc[e]);
        float p[8];
#pragma unroll
        for (int e = 0; e < 8; e++) p[e] = expf(acc[e] - m);
        int i0 = 0; float b0 = p[0];
#pragma unroll
        for (int e = 1; e < 8; e++) if (p[e] > b0) { b0 = p[e]; i0 = e; }
        int i1 = -1; float b1 = -1.f;
#pragma unroll
        for (int e = 0; e < 8; e++) if (e != i0 && p[e] > b1) { b1 = p[e]; i1 = e; }
        float inv = 1.f / (b0 + b1);
        int s0 = atomicAdd(&g_cnt[i0], 1); g_tok[i0 * Tt + s0] = t;
        int s1 = atomicAdd(&g_cnt[i1], 1); g_tok[i1 * Tt + s1] = t;
        g_sel[t] = make_int4(i0, s0, i1, s1);
        g_wt[t]  = make_float2(b0 * inv, b1 * inv);
    }
}

__global__ void scan_kernel() {
    if (threadIdx.x == 0) {
        int o = 0;
        for (int e = 0; e < Ee; e++) { g_off[e] = o; o += g_cnt[e]; }
    }
}

// x fp32 -> fp16 into g_xh (expert rows gathered in GEMM1 via g_tok)
__global__ void convx_kernel(const float* __restrict__ x) {
    int t = blockIdx.x;
    int i = threadIdx.x;               // 256 threads x 4 elems = 1024
    float4 v = *(const float4*)(x + (size_t)t * Hh + i * 4);
    __half2 h0 = __floats2half2_rn(v.x, v.y);
    __half2 h1 = __floats2half2_rn(v.z, v.w);
    *(uint2*)(g_xh + (size_t)t * Hh + i * 4) = make_uint2(*(unsigned*)&h0, *(unsigned*)&h1);
}

// transpose + fp16-convert: src[g][R][C] fp32 -> (g_w1t or g_w2t)[g][C][R] fp16.
// Destination selected INSIDE device code via template (never passed from host).
template <int W>
__global__ void transw_kernel(const float* __restrict__ base,
                              const float* __restrict__ exq) {
    constexpr int R = (W == 1) ? Hh : Ff;
    constexpr int C = (W == 1) ? Ff : Hh;
    __shared__ float tile[32][33];
    int g = blockIdx.z;
    const float* src = (g == 0) ? base : (exq + (size_t)(g - 1) * R * C);
    __half* d = ((W == 1) ? g_w1t : g_w2t) + (size_t)g * (size_t)R * C;
    int c0 = blockIdx.x * 32, r0 = blockIdx.y * 32;
    int tx = threadIdx.x, ty = threadIdx.y;
#pragma unroll
    for (int i = ty; i < 32; i += 8)
        tile[i][tx] = src[(size_t)(r0 + i) * C + c0 + tx];
    __syncthreads();
#pragma unroll
    for (int i = ty; i < 32; i += 8)
        d[(size_t)(c0 + i) * R + r0 + tx] = __float2half_rn(tile[tx][i]);
}

// ---------------- grouped fp16 GEMM: CTA 128x128, warp 64x32, 2-stage cp.async ----------------
// Fragments fed by ldmatrix.x4 (A: 4/step, B: 2/step) — mapping derived from the
// verified scalar-LDS round-14 kernel (same bits, same lanes).
// MODE 1: g_midh = fp16(silu(A @ W1t^T)),  A rows = tokens (g_tok gather for experts), K=H, N=F
// MODE 2: fp32 out: base -> Dout, experts -> g_expof. A = g_midh rows, K=F, N=H
// smem rows: 32 halves (16 words) padded to 20 words (80 B) -> 8-row ldmatrix groups conflict-free
#define ROW_W 20                      // words per smem row
#define A_STG_W (128 * ROW_W)         // 2560 words
#define STG_W (2 * A_STG_W)           // A + B = 5120 words = 20480 B; 2 stages = 40960 B

template <int MODE>
__global__ void __launch_bounds__(256, 2) gemm_kernel(
    float* __restrict__ Dout)
{
    constexpr int Kd = (MODE == 1) ? Hh : Ff;
    constexpr int Nd = (MODE == 1) ? Ff : Hh;
    constexpr int NT = Kd / 32;

    extern __shared__ unsigned sm[];
    __shared__ int s_arow[128];

    const int g  = blockIdx.z;
    const int tm = blockIdx.x;
    const int tn = blockIdx.y;
    const int e  = g - 1;
    const int cnt = (g == 0) ? Tt : g_cnt[e];
    if (tm * 128 >= cnt) return;
    const int off = (g == 0) ? 0 : g_off[e];

    const __half* Bt = ((MODE == 1) ? g_w1t : g_w2t) + (size_t)g * (size_t)Hh * Ff;
    const __half* Abase;
    float* OutpF = nullptr;
    __half* OutpH = nullptr;
    if (MODE == 1) {
        Abase = g_xh;                                   // token rows (gathered via s_arow)
        OutpH = g_midh + ((g == 0) ? 0 : (size_t)(Tt + off) * Ff);
    } else {
        Abase = g_midh + ((g == 0) ? 0 : (size_t)(Tt + off) * Ff);
        OutpF = (g == 0) ? Dout : (g_expof + (size_t)off * Hh);
    }

    const int tid  = threadIdx.x;
    const int lane = tid & 31;
    const int wid  = tid >> 5;
    const int wm = wid & 1, wn = wid >> 1;   // warps 2(m) x 4(n); warp tile 64x32
    const int g8 = lane >> 2, tq = lane & 3;

    // ---- A row indirection (token gather for MODE1 experts; identity otherwise) ----
    if (tid < 128) {
        int idx = tm * 128 + tid;
        int r = -1;
        if (idx < cnt) r = (MODE == 1) ? ((g == 0) ? idx : g_tok[e * Tt + idx]) : idx;
        s_arow[tid] = r;
    }
    __syncthreads();

    // ---- cp.async loader mapping: thread -> (row=tid>>2 [64/pass], chunk=tid&3) ----
    const int lrow = tid >> 2;
    const int lchk = tid & 3;

    const __half* aptr[2];
    int asz[2];
#pragma unroll
    for (int p = 0; p < 2; p++) {
        int srow = s_arow[p * 64 + lrow];
        aptr[p] = Abase + (size_t)(srow < 0 ? 0 : srow) * Kd + lchk * 8;
        asz[p] = (srow < 0) ? 0 : 16;
    }
    const __half* bptr[2];
#pragma unroll
    for (int p = 0; p < 2; p++)
        bptr[p] = Bt + (size_t)(tn * 128 + p * 64 + lrow) * Kd + lchk * 8;

    unsigned smemb = (unsigned)__cvta_generic_to_shared(sm);
    const unsigned a_dst = smemb + (lrow * ROW_W + lchk * 4) * 4;
    const unsigned b_dst = smemb + (A_STG_W + lrow * ROW_W + lchk * 4) * 4;

    auto issue = [&](int kidx) {
        unsigned so = (kidx & 1) * (STG_W * 4);
        int kh = kidx * 32;                       // k offset in halves
#pragma unroll
        for (int p = 0; p < 2; p++)
            cp16(a_dst + so + p * (64 * ROW_W * 4), aptr[p] + kh, asz[p]);
#pragma unroll
        for (int p = 0; p < 2; p++)
            cp16(b_dst + so + p * (64 * ROW_W * 4), bptr[p] + kh, 16);
        cp_commit();
    };

    issue(0);
    issue(1);

    // ---- ldmatrix per-lane base addresses ----
    // A x4 matrices (in reg order): (m0-7,k0-7),(m8-15,k0-7),(m0-7,k8-15),(m8-15,k8-15)
    //   lane groups 0-7/8-15/16-23/24-31 supply row addresses of those matrices.
    const int amid = lane >> 3, al8 = lane & 7;
    const unsigned a_lm = smemb + (unsigned)((wm * 64 + (amid & 1) * 8 + al8) * 80
                                             + (amid >> 1) * 16);
    // B x4 matrices: (j,k0-7),(j,k8-15),(j+1,k0-7),(j+1,k8-15) for j-group pair jp.
    const unsigned b_lm = smemb + (unsigned)(A_STG_W * 4
                                             + (wn * 32 + (amid >> 1) * 8 + al8) * 80
                                             + (amid & 1) * 16);

    float C[4][4][4];
#pragma unroll
    for (int i = 0; i < 4; i++)
#pragma unroll
        for (int j = 0; j < 4; j++)
#pragma unroll
            for (int q = 0; q < 4; q++) C[i][j][q] = 0.f;

#pragma unroll 1
    for (int it = 0; it < NT; it++) {
        // With tail empty-commits, wait<1> always implies k-chunk `it` resident.
        cp_wait<1>();
        __syncthreads();

        const unsigned so = (it & 1) * (STG_W * 4);

#pragma unroll
        for (int s = 0; s < 2; s++) {            // two k16 steps per 32-k chunk
            unsigned a[4][4], b[4][2];
#pragma unroll
            for (int i = 0; i < 4; i++)
                ldsm4(a[i][0], a[i][1], a[i][2], a[i][3],
                      a_lm + so + i * (16 * 80) + s * 32);
#pragma unroll
            for (int jp = 0; jp < 2; jp++) {
                unsigned r0, r1, r2, r3;
                ldsm4(r0, r1, r2, r3, b_lm + so + jp * (16 * 80) + s * 32);
                b[2 * jp][0] = r0; b[2 * jp][1] = r1;
                b[2 * jp + 1][0] = r2; b[2 * jp + 1][1] = r3;
            }
#pragma unroll
            for (int i = 0; i < 4; i++)
#pragma unroll
                for (int j = 0; j < 4; j++)
                    mmah(C[i][j], a[i], b[j]);
        }

        __syncthreads();
        if (it + 2 < NT) issue(it + 2);
        else             cp_commit();   // empty group: keeps group it from being newest
    }

    // ---- epilogue (global rows) ----
#pragma unroll
    for (int i = 0; i < 4; i++) {
        int gr0 = tm * 128 + wm * 64 + i * 16 + g8;
        int ok0 = gr0 < cnt;
        int ok1 = (gr0 + 8) < cnt;
#pragma unroll
        for (int j = 0; j < 4; j++) {
            int col = tn * 128 + wn * 32 + j * 8 + 2 * tq;
            float v0 = C[i][j][0], v1 = C[i][j][1];
            float v2 = C[i][j][2], v3 = C[i][j][3];
            if (MODE == 1) {
                v0 = v0 / (1.f + __expf(-v0));
                v1 = v1 / (1.f + __expf(-v1));
                v2 = v2 / (1.f + __expf(-v2));
                v3 = v3 / (1.f + __expf(-v3));
                __half2 h0 = __floats2half2_rn(v0, v1);
                __half2 h1 = __floats2half2_rn(v2, v3);
                if (ok0) *(unsigned*)(OutpH + (size_t)gr0 * Nd + col) = *(unsigned*)&h0;
                if (ok1) *(unsigned*)(OutpH + (size_t)(gr0 + 8) * Nd + col) = *(unsigned*)&h1;
            } else {
                if (ok0) *(float2*)(OutpF + (size_t)gr0 * Nd + col) = make_float2(v0, v1);
                if (ok1) *(float2*)(OutpF + (size_t)(gr0 + 8) * Nd + col) = make_float2(v2, v3);
            }
        }
    }
}

// out[t] += w0*expof[p0] + w1*expof[p1]   (fp32 expert outputs)
__global__ void combine_kernel(float* __restrict__ out) {
    int t = blockIdx.x;
    int4 s = g_sel[t];
    float2 w = g_wt[t];
    int p0 = g_off[s.x] + s.y;
    int p1 = g_off[s.z] + s.w;
    const float4* a = (const float4*)(g_expof + (size_t)p0 * Hh);
    const float4* b = (const float4*)(g_expof + (size_t)p1 * Hh);
    float4* o = (float4*)(out + (size_t)t * Hh);
    int i = threadIdx.x;   // 256 threads x 4 floats = 1024
    float4 ov = o[i], av = a[i], bv = b[i];
    ov.x += w.x * av.x + w.y * bv.x;
    ov.y += w.x * av.y + w.y * bv.y;
    ov.z += w.x * av.z + w.y * bv.z;
    ov.w += w.x * av.w + w.y * bv.w;
    o[i] = ov;
}

// ---------------- launch ----------------
extern "C" void kernel_launch(void* const* d_in, const int* in_sizes, int n_in,
                              void* d_out, int out_size)
{
    const float* x   = (const float*)d_in[0];
    const float* rw  = (const float*)d_in[1];
    const float* bw1 = (const float*)d_in[2];
    const float* bw2 = (const float*)d_in[3];
    const float* ew1 = (const float*)d_in[4];
    const float* ew2 = (const float*)d_in[5];
    float* out = (float*)d_out;

    // Idempotent (no static guards; graph-capture safe). Function symbols are OK here.
    const int smem_bytes = 2 * STG_W * 4;   // 40,960 B
    cudaFuncSetAttribute(gemm_kernel<1>, cudaFuncAttributeMaxDynamicSharedMemorySize, smem_bytes);
    cudaFuncSetAttribute(gemm_kernel<2>, cudaFuncAttributeMaxDynamicSharedMemorySize, smem_bytes);

    zero_cnt_kernel<<<1, 32>>>();
    router_kernel<<<Tt / 8, 256>>>(x, rw);
    scan_kernel<<<1, 32>>>();
    convx_kernel<<<Tt, 256>>>(x);

    // W1 [H][F] -> g_w1t [F][H] fp16 ; W2 [F][H] -> g_w2t [H][F] fp16
    transw_kernel<1><<<dim3(Ff / 32, Hh / 32, Ee + 1), dim3(32, 8)>>>(bw1, ew1);
    transw_kernel<2><<<dim3(Hh / 32, Ff / 32, Ee + 1), dim3(32, 8)>>>(bw2, ew2);

    // GEMM1: grid (m=32, n=F/128=32, groups=9)
    gemm_kernel<1><<<dim3(32, 32, Ee + 1), 256, smem_bytes>>>(nullptr);
    // GEMM2: grid (m=32, n=H/128=8, groups=9)
    gemm_kernel<2><<<dim3(32, 8, Ee + 1), 256, smem_bytes>>>(out);

    combine_kernel<<<Tt, 256>>>(out);
}

// round 16
// speedup vs baseline: 1.7000x; 1.1599x over previous
#include <cuda_runtime.h>
#include <cuda_fp16.h>
#include <math.h>

// Problem constants (B=2,S=2048 -> T=4096; H=1024; F=4096; E=8; TOP_K=2)
#define Tt 4096
#define Hh 1024
#define Ff 4096
#define Ee 8

// ---------------- scratch (static device globals, ~294 MB) ----------------
// RULE (session finding): __device__ symbols must NEVER be passed as kernel
// arguments from host code (host shadow address != device address).
// All globals below are referenced ONLY inside device code.
__device__ __half  g_w1t[(size_t)(Ee + 1) * Ff * Hh];   // W1^T per group: [g][F][H] fp16
__device__ __half  g_w2t[(size_t)(Ee + 1) * Hh * Ff];   // W2^T per group: [g][H][F] fp16
__device__ __half  g_midh[(size_t)3 * Tt * Ff];         // fp16 mid: base [0,T), experts [T,3T)
__device__ __half  g_xh [(size_t)Tt * Hh];              // fp16 x
__device__ float   g_expof[(size_t)2 * Tt * Hh];        // fp32 unweighted expert outputs
__device__ int     g_tok[Ee * Tt];
__device__ int     g_cnt[Ee];
__device__ int     g_off[Ee];
__device__ int4    g_sel[Tt];                           // (e0, slot0, e1, slot1)
__device__ float2  g_wt[Tt];

// ---------------- PTX helpers ----------------
__device__ __forceinline__ void mmah(float* c, const unsigned* a, const unsigned* b) {
    asm volatile(
        "mma.sync.aligned.m16n8k16.row.col.f32.f16.f16.f32 "
        "{%0,%1,%2,%3}, {%4,%5,%6,%7}, {%8,%9}, {%0,%1,%2,%3};"
        : "+f"(c[0]), "+f"(c[1]), "+f"(c[2]), "+f"(c[3])
        : "r"(a[0]), "r"(a[1]), "r"(a[2]), "r"(a[3]),
          "r"(b[0]), "r"(b[1]));
}
__device__ __forceinline__ void ldsm4(unsigned& r0, unsigned& r1, unsigned& r2, unsigned& r3,
                                      unsigned addr) {
    asm volatile("ldmatrix.sync.aligned.m8n8.x4.shared.b16 {%0,%1,%2,%3}, [%4];"
                 : "=r"(r0), "=r"(r1), "=r"(r2), "=r"(r3) : "r"(addr));
}
__device__ __forceinline__ void cp16(unsigned smem_addr, const void* gptr, int srcsize) {
    asm volatile("cp.async.cg.shared.global [%0], [%1], 16, %2;"
                 :: "r"(smem_addr), "l"(gptr), "r"(srcsize));
}
__device__ __forceinline__ void cp_commit() { asm volatile("cp.async.commit_group;"); }
template <int N>
__device__ __forceinline__ void cp_wait() {
    asm volatile("cp.async.wait_group %0;" :: "n"(N));
}

// ---------------- small kernels ----------------
__global__ void zero_cnt_kernel() {
    if (threadIdx.x < Ee) g_cnt[threadIdx.x] = 0;
}

// one warp per token: logits, softmax, top2, renormalize, slot assignment (fp32 exact)
__global__ void router_kernel(const float* __restrict__ x, const float* __restrict__ rw) {
    int wid  = threadIdx.x >> 5;
    int lane = threadIdx.x & 31;
    int t = blockIdx.x * 8 + wid;
    if (t >= Tt) return;

    float acc[8] = {0.f,0.f,0.f,0.f,0.f,0.f,0.f,0.f};
    const float* xr = x + (size_t)t * Hh;
    for (int h = lane; h < Hh; h += 32) {
        float xv = xr[h];
        float4 r0 = *(const float4*)(rw + (size_t)h * Ee);
        float4 r1 = *(const float4*)(rw + (size_t)h * Ee + 4);
        acc[0] += xv * r0.x; acc[1] += xv * r0.y; acc[2] += xv * r0.z; acc[3] += xv * r0.w;
        acc[4] += xv * r1.x; acc[5] += xv * r1.y; acc[6] += xv * r1.z; acc[7] += xv * r1.w;
    }
#pragma unroll
    for (int e = 0; e < 8; e++)
#pragma unroll
        for (int o = 16; o > 0; o >>= 1)
            acc[e] += __shfl_xor_sync(0xffffffffu, acc[e], o);

    if (lane == 0) {
        float m = acc[0];
#pragma unroll
        for (int e = 1; e < 8; e++) m = fmaxf(m, acc[e]);
        float p[8];
#pragma unroll
        for (int e = 0; e < 8; e++) p[e] = expf(acc[e] - m);
        int i0 = 0; float b0 = p[0];
#pragma unroll
        for (int e = 1; e < 8; e++) if (p[e] > b0) { b0 = p[e]; i0 = e; }
        int i1 = -1; float b1 = -1.f;
#pragma unroll
        for (int e = 0; e < 8; e++) if (e != i0 && p[e] > b1) { b1 = p[e]; i1 = e; }
        float inv = 1.f / (b0 + b1);
        int s0 = atomicAdd(&g_cnt[i0], 1); g_tok[i0 * Tt + s0] = t;
        int s1 = atomicAdd(&g_cnt[i1], 1); g_tok[i1 * Tt + s1] = t;
        g_sel[t] = make_int4(i0, s0, i1, s1);
        g_wt[t]  = make_float2(b0 * inv, b1 * inv);
    }
}

__global__ void scan_kernel() {
    if (threadIdx.x == 0) {
        int o = 0;
        for (int e = 0; e < Ee; e++) { g_off[e] = o; o += g_cnt[e]; }
    }
}

// x fp32 -> fp16 into g_xh (expert rows gathered in GEMM1 via g_tok)
__global__ void convx_kernel(const float* __restrict__ x) {
    int t = blockIdx.x;
    int i = threadIdx.x;               // 256 threads x 4 elems = 1024
    float4 v = *(const float4*)(x + (size_t)t * Hh + i * 4);
    __half2 h0 = __floats2half2_rn(v.x, v.y);
    __half2 h1 = __floats2half2_rn(v.z, v.w);
    *(uint2*)(g_xh + (size_t)t * Hh + i * 4) = make_uint2(*(unsigned*)&h0, *(unsigned*)&h1);
}

// transpose + fp16-convert: src[g][R][C] fp32 -> (g_w1t or g_w2t)[g][C][R] fp16.
// Destination selected INSIDE device code via template (never passed from host).
template <int W>
__global__ void transw_kernel(const float* __restrict__ base,
                              const float* __restrict__ exq) {
    constexpr int R = (W == 1) ? Hh : Ff;
    constexpr int C = (W == 1) ? Ff : Hh;
    __shared__ float tile[32][33];
    int g = blockIdx.z;
    const float* src = (g == 0) ? base : (exq + (size_t)(g - 1) * R * C);
    __half* d = ((W == 1) ? g_w1t : g_w2t) + (size_t)g * (size_t)R * C;
    int c0 = blockIdx.x * 32, r0 = blockIdx.y * 32;
    int tx = threadIdx.x, ty = threadIdx.y;
#pragma unroll
    for (int i = ty; i < 32; i += 8)
        tile[i][tx] = src[(size_t)(r0 + i) * C + c0 + tx];
    __syncthreads();
#pragma unroll
    for (int i = ty; i < 32; i += 8)
        d[(size_t)(c0 + i) * R + r0 + tx] = __float2half_rn(tile[tx][i]);
}

// ---------------- grouped fp16 GEMM: CTA 128x128, warp 64x32, K-chunk 64, 2-stage ----------------
// Fragments fed by ldmatrix.x4; mapping identical to verified R15 kernel (just larger k-chunk).
// MODE 1: g_midh = fp16(silu(A @ W1t^T)),  A rows = tokens (g_tok gather for experts), K=H, N=F
// MODE 2: fp32 out: base -> Dout, experts -> g_expof. A = g_midh rows, K=F, N=H
// smem rows: 64 halves (32 words) padded to 36 words (144 B)
//   ldmatrix 8-row groups: word offsets 36r mod 32 = {0,4,...,28}, each lane spans 4 words
//   -> all 32 banks covered exactly once: conflict-free.
#define KCH 64
#define ROW_W 36                      // words per smem row
#define A_STG_W (128 * ROW_W)         // 4608 words
#define STG_W (2 * A_STG_W)           // 9216 words = 36864 B; 2 stages = 73728 B

template <int MODE>
__global__ void __launch_bounds__(256, 2) gemm_kernel(
    float* __restrict__ Dout)
{
    constexpr int Kd = (MODE == 1) ? Hh : Ff;
    constexpr int Nd = (MODE == 1) ? Ff : Hh;
    constexpr int NT = Kd / KCH;

    extern __shared__ unsigned sm[];
    __shared__ int s_arow[128];

    const int g  = blockIdx.z;
    const int tm = blockIdx.x;
    const int tn = blockIdx.y;
    const int e  = g - 1;
    const int cnt = (g == 0) ? Tt : g_cnt[e];
    if (tm * 128 >= cnt) return;
    const int off = (g == 0) ? 0 : g_off[e];

    const __half* Bt = ((MODE == 1) ? g_w1t : g_w2t) + (size_t)g * (size_t)Hh * Ff;
    const __half* Abase;
    float* OutpF = nullptr;
    __half* OutpH = nullptr;
    if (MODE == 1) {
        Abase = g_xh;                                   // token rows (gathered via s_arow)
        OutpH = g_midh + ((g == 0) ? 0 : (size_t)(Tt + off) * Ff);
    } else {
        Abase = g_midh + ((g == 0) ? 0 : (size_t)(Tt + off) * Ff);
        OutpF = (g == 0) ? Dout : (g_expof + (size_t)off * Hh);
    }

    const int tid  = threadIdx.x;
    const int lane = tid & 31;
    const int wid  = tid >> 5;
    const int wm = wid & 1, wn = wid >> 1;   // warps 2(m) x 4(n); warp tile 64x32
    const int g8 = lane >> 2, tq = lane & 3;

    // ---- A row indirection (token gather for MODE1 experts; identity otherwise) ----
    if (tid < 128) {
        int idx = tm * 128 + tid;
        int r = -1;
        if (idx < cnt) r = (MODE == 1) ? ((g == 0) ? idx : g_tok[e * Tt + idx]) : idx;
        s_arow[tid] = r;
    }
    __syncthreads();

    // ---- cp.async loader: thread -> (row=tid>>3 [32 rows/pass], chunk=tid&7); 4 passes each ----
    const int lrow = tid >> 3;
    const int lchk = tid & 7;

    const __half* aptr[4];
    int asz[4];
#pragma unroll
    for (int p = 0; p < 4; p++) {
        int srow = s_arow[p * 32 + lrow];
        aptr[p] = Abase + (size_t)(srow < 0 ? 0 : srow) * Kd + lchk * 8;
        asz[p] = (srow < 0) ? 0 : 16;
    }
    const __half* bptr[4];
#pragma unroll
    for (int p = 0; p < 4; p++)
        bptr[p] = Bt + (size_t)(tn * 128 + p * 32 + lrow) * Kd + lchk * 8;

    unsigned smemb = (unsigned)__cvta_generic_to_shared(sm);
    const unsigned a_dst = smemb + (lrow * ROW_W + lchk * 4) * 4;
    const unsigned b_dst = smemb + (A_STG_W + lrow * ROW_W + lchk * 4) * 4;

    auto issue = [&](int kidx) {
        unsigned so = (kidx & 1) * (STG_W * 4);
        int kh = kidx * KCH;                      // k offset in halves
#pragma unroll
        for (int p = 0; p < 4; p++)
            cp16(a_dst + so + p * (32 * ROW_W * 4), aptr[p] + kh, asz[p]);
#pragma unroll
        for (int p = 0; p < 4; p++)
            cp16(b_dst + so + p * (32 * ROW_W * 4), bptr[p] + kh, 16);
        cp_commit();
    };

    issue(0);
    issue(1);

    // ---- ldmatrix per-lane base addresses (row stride 144 B) ----
    const int amid = lane >> 3, al8 = lane & 7;
    const unsigned a_lm = smemb + (unsigned)((wm * 64 + (amid & 1) * 8 + al8) * 144
                                             + (amid >> 1) * 16);
    const unsigned b_lm = smemb + (unsigned)(A_STG_W * 4
                                             + (wn * 32 + (amid >> 1) * 8 + al8) * 144
                                             + (amid & 1) * 16);

    float C[4][4][4];
#pragma unroll
    for (int i = 0; i < 4; i++)
#pragma unroll
        for (int j = 0; j < 4; j++)
#pragma unroll
            for (int q = 0; q < 4; q++) C[i][j][q] = 0.f;

#pragma unroll 1
    for (int it = 0; it < NT; it++) {
        // With tail empty-commits, wait<1> always implies k-chunk `it` resident.
        cp_wait<1>();
        __syncthreads();

        const unsigned so = (it & 1) * (STG_W * 4);

#pragma unroll
        for (int s = 0; s < 4; s++) {            // four k16 steps per 64-k chunk
            unsigned a[4][4], b[4][2];
#pragma unroll
            for (int i = 0; i < 4; i++)
                ldsm4(a[i][0], a[i][1], a[i][2], a[i][3],
                      a_lm + so + i * (16 * 144) + s * 32);
#pragma unroll
            for (int jp = 0; jp < 2; jp++) {
                unsigned r0, r1, r2, r3;
                ldsm4(r0, r1, r2, r3, b_lm + so + jp * (16 * 144) + s * 32);
                b[2 * jp][0] = r0; b[2 * jp][1] = r1;
                b[2 * jp + 1][0] = r2; b[2 * jp + 1][1] = r3;
            }
#pragma unroll
            for (int i = 0; i < 4; i++)
#pragma unroll
                for (int j = 0; j < 4; j++)
                    mmah(C[i][j], a[i], b[j]);
        }

        __syncthreads();
        if (it + 2 < NT) issue(it + 2);
        else             cp_commit();   // empty group: keeps group it from being newest
    }

    // ---- epilogue (global rows) ----
#pragma unroll
    for (int i = 0; i < 4; i++) {
        int gr0 = tm * 128 + wm * 64 + i * 16 + g8;
        int ok0 = gr0 < cnt;
        int ok1 = (gr0 + 8) < cnt;
#pragma unroll
        for (int j = 0; j < 4; j++) {
            int col = tn * 128 + wn * 32 + j * 8 + 2 * tq;
            float v0 = C[i][j][0], v1 = C[i][j][1];
            float v2 = C[i][j][2], v3 = C[i][j][3];
            if (MODE == 1) {
                v0 = v0 / (1.f + __expf(-v0));
                v1 = v1 / (1.f + __expf(-v1));
                v2 = v2 / (1.f + __expf(-v2));
                v3 = v3 / (1.f + __expf(-v3));
                __half2 h0 = __floats2half2_rn(v0, v1);
                __half2 h1 = __floats2half2_rn(v2, v3);
                if (ok0) *(unsigned*)(OutpH + (size_t)gr0 * Nd + col) = *(unsigned*)&h0;
                if (ok1) *(unsigned*)(OutpH + (size_t)(gr0 + 8) * Nd + col) = *(unsigned*)&h1;
            } else {
                if (ok0) *(float2*)(OutpF + (size_t)gr0 * Nd + col) = make_float2(v0, v1);
                if (ok1) *(float2*)(OutpF + (size_t)(gr0 + 8) * Nd + col) = make_float2(v2, v3);
            }
        }
    }
}

// out[t] += w0*expof[p0] + w1*expof[p1]   (fp32 expert outputs)
__global__ void combine_kernel(float* __restrict__ out) {
    int t = blockIdx.x;
    int4 s = g_sel[t];
    float2 w = g_wt[t];
    int p0 = g_off[s.x] + s.y;
    int p1 = g_off[s.z] + s.w;
    const float4* a = (const float4*)(g_expof + (size_t)p0 * Hh);
    const float4* b = (const float4*)(g_expof + (size_t)p1 * Hh);
    float4* o = (float4*)(out + (size_t)t * Hh);
    int i = threadIdx.x;   // 256 threads x 4 floats = 1024
    float4 ov = o[i], av = a[i], bv = b[i];
    ov.x += w.x * av.x + w.y * bv.x;
    ov.y += w.x * av.y + w.y * bv.y;
    ov.z += w.x * av.z + w.y * bv.z;
    ov.w += w.x * av.w + w.y * bv.w;
    o[i] = ov;
}

// ---------------- launch ----------------
extern "C" void kernel_launch(void* const* d_in, const int* in_sizes, int n_in,
                              void* d_out, int out_size)
{
    const float* x   = (const float*)d_in[0];
    const float* rw  = (const float*)d_in[1];
    const float* bw1 = (const float*)d_in[2];
    const float* bw2 = (const float*)d_in[3];
    const float* ew1 = (const float*)d_in[4];
    const float* ew2 = (const float*)d_in[5];
    float* out = (float*)d_out;

    // Idempotent (no static guards; graph-capture safe). Function symbols are OK here.
    const int smem_bytes = 2 * STG_W * 4;   // 73,728 B
    cudaFuncSetAttribute(gemm_kernel<1>, cudaFuncAttributeMaxDynamicSharedMemorySize, smem_bytes);
    cudaFuncSetAttribute(gemm_kernel<2>, cudaFuncAttributeMaxDynamicSharedMemorySize, smem_bytes);

    zero_cnt_kernel<<<1, 32>>>();
    router_kernel<<<Tt / 8, 256>>>(x, rw);
    scan_kernel<<<1, 32>>>();
    convx_kernel<<<Tt, 256>>>(x);

    // W1 [H][F] -> g_w1t [F][H] fp16 ; W2 [F][H] -> g_w2t [H][F] fp16
    transw_kernel<1><<<dim3(Ff / 32, Hh / 32, Ee + 1), dim3(32, 8)>>>(bw1, ew1);
    transw_kernel<2><<<dim3(Hh / 32, Ff / 32, Ee + 1), dim3(32, 8)>>>(bw2, ew2);

    // GEMM1: grid (m=32, n=F/128=32, groups=9)
    gemm_kernel<1><<<dim3(32, 32, Ee + 1), 256, smem_bytes>>>(nullptr);
    // GEMM2: grid (m=32, n=H/128=8, groups=9)
    gemm_kernel<2><<<dim3(32, 8, Ee + 1), 256, smem_bytes>>>(out);

    combine_kernel<<<Tt, 256>>>(out);
}